// round 13
// baseline (speedup 1.0000x reference)
#include <cuda_runtime.h>
#include <cuda_fp16.h>
#include <cstdint>

// ============================================================
// IndRNN on GB300 (base-PTX tensor path):
//   xp = x @ W     -> single-pass FP16 mma.sync (m16n8k16), fp32 accum
//   out = scan(relu(xp_t + b + u*h))
// R13: A pre-converted to fp16 once (g_Ah); GEMM mainloop is pure
// cp.async + ldmatrix + mma (no LDG/CVT/STS). CTA 128x256, warp 64x64,
// BK=64, 8 stages, double-buffered. Scan: float2 chains.
// ============================================================

__device__ __half g_Wt[512 * 512];          // W^T fp16 [n][k]
__device__ __half g_Ah[65536 * 512];        // x fp16 [m][k] (64 MB scratch)

__device__ __forceinline__ uint32_t smem_u32(const void* p) {
    uint32_t a;
    asm("{ .reg .u64 t; cvta.to.shared.u64 t, %1; cvt.u32.u64 %0, t; }"
        : "=r"(a) : "l"(p));
    return a;
}

__device__ __forceinline__ void ldm_x4(uint32_t r[4], uint32_t addr) {
    asm volatile("ldmatrix.sync.aligned.m8n8.x4.shared.b16 {%0,%1,%2,%3}, [%4];"
                 : "=r"(r[0]), "=r"(r[1]), "=r"(r[2]), "=r"(r[3]) : "r"(addr));
}

__device__ __forceinline__ void mma_f16(float c[4], const uint32_t a[4],
                                        const uint32_t b0, const uint32_t b1) {
    asm volatile(
        "mma.sync.aligned.m16n8k16.row.col.f32.f16.f16.f32 "
        "{%0,%1,%2,%3}, {%4,%5,%6,%7}, {%8,%9}, {%0,%1,%2,%3};"
        : "+f"(c[0]), "+f"(c[1]), "+f"(c[2]), "+f"(c[3])
        : "r"(a[0]), "r"(a[1]), "r"(a[2]), "r"(a[3]), "r"(b0), "r"(b1));
}

__device__ __forceinline__ void cp16(uint32_t saddr, const void* g) {
    asm volatile("cp.async.cg.shared.global [%0], [%1], 16;"
                 :: "r"(saddr), "l"(g) : "memory");
}
__device__ __forceinline__ void cp_commit() {
    asm volatile("cp.async.commit_group;" ::: "memory");
}
__device__ __forceinline__ void cp_wait0() {
    asm volatile("cp.async.wait_group 0;" ::: "memory");
}

__device__ __forceinline__ uint32_t h2_bits(__half2 v) {
    return *reinterpret_cast<uint32_t*>(&v);
}

// ---------------- W prepass: transpose + fp16 round ----------------
__global__ __launch_bounds__(256) void conv_w(const float* __restrict__ W) {
    int idx = blockIdx.x * blockDim.x + threadIdx.x;  // 0..262143
    int n = idx >> 9;
    int k = idx & 511;
    g_Wt[idx] = __float2half_rn(W[k * 512 + n]);
}

// ---------------- A prepass: fp32 -> fp16, 8 elems/thread ----------------
__global__ __launch_bounds__(256) void conv_x(const float* __restrict__ X) {
    size_t i8 = ((size_t)blockIdx.x * blockDim.x + threadIdx.x) * 8;
    float4 a = *reinterpret_cast<const float4*>(X + i8);
    float4 b = *reinterpret_cast<const float4*>(X + i8 + 4);
    uint4 v;
    v.x = h2_bits(__floats2half2_rn(a.x, a.y));
    v.y = h2_bits(__floats2half2_rn(a.z, a.w));
    v.z = h2_bits(__floats2half2_rn(b.x, b.y));
    v.w = h2_bits(__floats2half2_rn(b.z, b.w));
    *reinterpret_cast<uint4*>(g_Ah + i8) = v;
}

// ---------------- FP16 GEMM: C[65536,512] = A[65536,512] @ W ----------------
// BK=64: smem rows = 64 halves (128B) + 16B pad = 144B -> conflict-free
#define ROWB      144
#define A_MAT     (128 * ROWB)            // 18432
#define B_MAT     (256 * ROWB)            // 36864
#define OFF_A     0
#define OFF_B     A_MAT
#define STAGE_SZ  (A_MAT + B_MAT)         // 55296
#define GEMM_SMEM (2 * STAGE_SZ)          // 110592

__global__ __launch_bounds__(256, 1) void indrnn_gemm_f16(
    float* __restrict__ C)         // [65536, 512]
{
    extern __shared__ char smem[];
    const uint32_t sb = smem_u32(smem);
    const int tid = (int)threadIdx.x;
    const int wid = tid >> 5;
    const int lane = tid & 31;

    const int bn = blockIdx.x * 256;   // 2 n-tiles (W stays L2-resident)
    const int bm = blockIdx.y * 128;   // 512 m-tiles

    const int wm = (wid & 1) * 64;     // warp m-offset
    const int wn = (wid >> 1) * 64;    // warp n-offset

    const int grp = lane >> 2;         // epilogue row group
    const int tg  = lane & 3;

    // ldmatrix lane address components
    const uint32_t lrow = (uint32_t)(lane & 15);
    const uint32_t lkb  = (uint32_t)((lane >> 4) * 16);

    // A cp.async: thread owns half a row (32 halves = 4x16B)
    const int arow = tid >> 1;
    const int ah   = tid & 1;
    const __half* agp = g_Ah + (size_t)(bm + arow) * 512 + ah * 32;
    const uint32_t aso = (uint32_t)(arow * ROWB + ah * 64);

    // B cp.async: thread owns one n-row (64 halves = 8x16B)
    const __half* bgp = g_Wt + (size_t)(bn + tid) * 512;
    const uint32_t bso = (uint32_t)(tid * ROWB);

    float acc[4][8][4];   // [mblock][ngroup][reg] = 128 regs
    #pragma unroll
    for (int i = 0; i < 4; i++)
        #pragma unroll
        for (int j = 0; j < 8; j++)
            #pragma unroll
            for (int q = 0; q < 4; q++)
                acc[i][j][q] = 0.0f;

    // ---- prologue: stage 0 ----
    {
        #pragma unroll
        for (int c = 0; c < 4; c++)
            cp16(sb + OFF_A + aso + c * 16, agp + c * 8);
        #pragma unroll
        for (int c = 0; c < 8; c++)
            cp16(sb + OFF_B + bso + c * 16, bgp + c * 8);
        cp_commit();
        cp_wait0();
    }
    __syncthreads();

    #pragma unroll 1
    for (int ch = 0; ch < 8; ch++) {
        const uint32_t st = sb + (uint32_t)(ch & 1) * STAGE_SZ;
        const uint32_t nst = sb + (uint32_t)((ch + 1) & 1) * STAGE_SZ;

        // ---- issue next stage's loads ----
        if (ch < 7) {
            const int koff = (ch + 1) * 64;
            #pragma unroll
            for (int c = 0; c < 4; c++)
                cp16(nst + OFF_A + aso + c * 16, agp + koff + c * 8);
            #pragma unroll
            for (int c = 0; c < 8; c++)
                cp16(nst + OFF_B + bso + c * 16, bgp + koff + c * 8);
            cp_commit();
        }

        // ---- compute this stage: 4 k16-steps ----
        #pragma unroll
        for (int ks = 0; ks < 4; ks++) {
            const uint32_t kb = (uint32_t)(ks * 32) + lkb;
            uint32_t am[4][4];
            uint32_t bh[8][2];

            #pragma unroll
            for (int mb = 0; mb < 4; mb++)
                ldm_x4(am[mb], st + OFF_A +
                               (uint32_t)((wm + mb * 16 + (int)lrow) * ROWB) + kb);
            #pragma unroll
            for (int nb = 0; nb < 4; nb++) {
                uint32_t r[4];
                ldm_x4(r, st + OFF_B +
                          (uint32_t)((wn + nb * 16 + (int)lrow) * ROWB) + kb);
                bh[2 * nb][0] = r[0]; bh[2 * nb + 1][0] = r[1];
                bh[2 * nb][1] = r[2]; bh[2 * nb + 1][1] = r[3];
            }
            #pragma unroll
            for (int mb = 0; mb < 4; mb++)
                #pragma unroll
                for (int ng = 0; ng < 8; ng++)
                    mma_f16(acc[mb][ng], am[mb], bh[ng][0], bh[ng][1]);
        }

        // ---- swing buffers ----
        if (ch < 7) {
            cp_wait0();
            __syncthreads();
        }
    }

    // ---- epilogue: acc regs -> C ----
    {
        #pragma unroll
        for (int mb = 0; mb < 4; mb++) {
            const int row0 = bm + wm + mb * 16 + grp;
            #pragma unroll
            for (int ng = 0; ng < 8; ng++) {
                const int col = bn + wn + ng * 8 + tg * 2;
                *reinterpret_cast<float2*>(&C[(size_t)row0 * 512 + col]) =
                    make_float2(acc[mb][ng][0], acc[mb][ng][1]);
                *reinterpret_cast<float2*>(&C[(size_t)(row0 + 8) * 512 + col]) =
                    make_float2(acc[mb][ng][2], acc[mb][ng][3]);
            }
        }
    }
}

// ---------------- scan: h_t = relu(xp_t + b + u*h_{t-1}), in-place ----------------
// float2 chains: each thread owns 2 consecutive r.
__global__ __launch_bounds__(128) void indrnn_scan(
    float* __restrict__ xp,          // [64, 1024, 512]
    const float* __restrict__ u,     // [512]
    const float* __restrict__ bias)  // [512]
{
    const int T = 1024;
    const int R = 512;
    int idx = blockIdx.x * blockDim.x + threadIdx.x;  // 0..16383
    int b = idx >> 8;            // 0..63
    int r2 = (idx & 255) * 2;    // 0,2,..,510

    float2 uu = *reinterpret_cast<const float2*>(u + r2);
    float2 bb = *reinterpret_cast<const float2*>(bias + r2);
    float h0 = 1.0f, h1 = 1.0f;
    float2* p = reinterpret_cast<float2*>(xp + (size_t)b * T * R + r2);

    #pragma unroll 1
    for (int t0 = 0; t0 < T; t0 += 32) {
        float2 v[32];
        #pragma unroll
        for (int j = 0; j < 32; j++)
            v[j] = p[(size_t)(t0 + j) * 256];
        #pragma unroll
        for (int j = 0; j < 32; j++) {
            h0 = fmaxf(fmaf(uu.x, h0, v[j].x + bb.x), 0.0f);
            h1 = fmaxf(fmaf(uu.y, h1, v[j].y + bb.y), 0.0f);
            v[j].x = h0; v[j].y = h1;
        }
        #pragma unroll
        for (int j = 0; j < 32; j++)
            p[(size_t)(t0 + j) * 256] = v[j];
    }
}

// ---------------- launch ----------------
extern "C" void kernel_launch(void* const* d_in, const int* in_sizes, int n_in,
                              void* d_out, int out_size)
{
    const float* x  = (const float*)d_in[0];  // [64,1024,512]
    const float* W  = (const float*)d_in[1];  // [512,512]
    const float* u  = (const float*)d_in[2];  // [512]
    const float* b  = (const float*)d_in[3];  // [512]
    float* out = (float*)d_out;               // [64,1024,512]

    (void)in_sizes; (void)n_in; (void)out_size;

    cudaFuncSetAttribute(indrnn_gemm_f16,
                         cudaFuncAttributeMaxDynamicSharedMemorySize, GEMM_SMEM);

    conv_w<<<1024, 256>>>(W);
    conv_x<<<16384, 256>>>(x);   // 33.5M elems, 8 per thread

    dim3 ggrid(2, 512);  // x = n-tile, y = m-tile
    indrnn_gemm_f16<<<ggrid, 256, GEMM_SMEM>>>(out);

    indrnn_scan<<<128, 128>>>(out, u, b);
}

// round 14
// speedup vs baseline: 1.1981x; 1.1981x over previous
#include <cuda_runtime.h>
#include <cuda_fp16.h>
#include <cstdint>

// ============================================================
// IndRNN on GB300 (base-PTX tensor path):
//   xp = x @ W     -> single-pass FP16 mma.sync (m16n8k16), fp32 accum
//                     (R10 GEMM verbatim; it sits at the legacy-mma
//                      pipe ceiling per R11/R12/R13 falsifications)
//   xp stored as fp16 scratch (halves GEMM-write + scan-read DRAM)
//   out = scan(relu(xp_t + b + u*h)) -> fp32 output
// ============================================================

__device__ __half g_Wt[512 * 512];       // W^T fp16 [n][k]
__device__ __half g_xp[65536 * 512];     // xp fp16 scratch (64 MB)

__device__ __forceinline__ uint32_t smem_u32(const void* p) {
    uint32_t a;
    asm("{ .reg .u64 t; cvta.to.shared.u64 t, %1; cvt.u32.u64 %0, t; }"
        : "=r"(a) : "l"(p));
    return a;
}

__device__ __forceinline__ void ldm_x4(uint32_t r[4], uint32_t addr) {
    asm volatile("ldmatrix.sync.aligned.m8n8.x4.shared.b16 {%0,%1,%2,%3}, [%4];"
                 : "=r"(r[0]), "=r"(r[1]), "=r"(r[2]), "=r"(r[3]) : "r"(addr));
}

__device__ __forceinline__ void mma_f16(float c[4], const uint32_t a[4],
                                        const uint32_t b0, const uint32_t b1) {
    asm volatile(
        "mma.sync.aligned.m16n8k16.row.col.f32.f16.f16.f32 "
        "{%0,%1,%2,%3}, {%4,%5,%6,%7}, {%8,%9}, {%0,%1,%2,%3};"
        : "+f"(c[0]), "+f"(c[1]), "+f"(c[2]), "+f"(c[3])
        : "r"(a[0]), "r"(a[1]), "r"(a[2]), "r"(a[3]), "r"(b0), "r"(b1));
}

__device__ __forceinline__ void cp16(uint32_t saddr, const void* g) {
    asm volatile("cp.async.cg.shared.global [%0], [%1], 16;"
                 :: "r"(saddr), "l"(g) : "memory");
}
__device__ __forceinline__ void cp_commit() {
    asm volatile("cp.async.commit_group;" ::: "memory");
}
__device__ __forceinline__ void cp_wait0() {
    asm volatile("cp.async.wait_group 0;" ::: "memory");
}

__device__ __forceinline__ uint32_t h2_bits(__half2 v) {
    return *reinterpret_cast<uint32_t*>(&v);
}

// ---------------- W prepass: transpose + fp16 round ----------------
__global__ __launch_bounds__(256) void conv_w(const float* __restrict__ W) {
    int idx = blockIdx.x * blockDim.x + threadIdx.x;  // 0..262143
    int n = idx >> 9;
    int k = idx & 511;
    g_Wt[idx] = __float2half_rn(W[k * 512 + n]);
}

// ---------------- FP16 GEMM: xp[65536,512] = A[65536,512] @ W ----------------
// R10 structure: CTA 128x256, warp 64x64, BK=32, double-buffered,
// cp.async for B, inline fp32->fp16 for A, 80B padded rows.
#define ROWB      80
#define A_MAT     (128 * ROWB)            // 10240
#define B_MAT     (256 * ROWB)            // 20480
#define OFF_A     0
#define OFF_B     A_MAT
#define STAGE_SZ  (A_MAT + B_MAT)         // 30720
#define GEMM_SMEM (2 * STAGE_SZ)          // 61440

__global__ __launch_bounds__(256, 1) void indrnn_gemm_f16(
    const float* __restrict__ A)   // [65536, 512]
{
    extern __shared__ char smem[];
    const uint32_t sb = smem_u32(smem);
    const int tid = (int)threadIdx.x;
    const int wid = tid >> 5;
    const int lane = tid & 31;

    const int bn = blockIdx.x * 256;   // 2 n-tiles (W stays L2-resident)
    const int bm = blockIdx.y * 128;   // 512 m-tiles

    const int wm = (wid & 1) * 64;     // warp m-offset
    const int wn = (wid >> 1) * 64;    // warp n-offset

    const int grp = lane >> 2;         // epilogue row group
    const int tg  = lane & 3;

    // ldmatrix lane address components
    const uint32_t lrow = (uint32_t)(lane & 15);
    const uint32_t lkb  = (uint32_t)((lane >> 4) * 16);

    // A staging: thread owns 16 consecutive k of one row
    const int srow = tid >> 1;         // 0..127
    const int sh   = tid & 1;
    const float* aptr = A + (size_t)(bm + srow) * 512 + sh * 16;
    const uint32_t aswoff = (uint32_t)(srow * ROWB + sh * 32);

    // B staging via cp.async: thread owns one n-row (32 halves = 4x16B)
    const __half* bgp = g_Wt + (size_t)(bn + tid) * 512;
    const uint32_t bswrow = (uint32_t)(tid * ROWB);

    float acc[4][8][4];   // [mblock][ngroup][reg] = 128 regs
    #pragma unroll
    for (int i = 0; i < 4; i++)
        #pragma unroll
        for (int j = 0; j < 8; j++)
            #pragma unroll
            for (int q = 0; q < 4; q++)
                acc[i][j][q] = 0.0f;

    float4 pa[4];  // A prefetch regs (16 fp32)

    // ---- prologue: stage 0 ----
    {
        #pragma unroll
        for (int c = 0; c < 4; c++)
            cp16(sb + OFF_B + bswrow + c * 16, bgp + c * 8);
        cp_commit();
        #pragma unroll
        for (int i = 0; i < 4; i++)
            pa[i] = reinterpret_cast<const float4*>(aptr)[i];
        const float* f = reinterpret_cast<const float*>(pa);
        uint32_t hw[8];
        #pragma unroll
        for (int i = 0; i < 8; i++)
            hw[i] = h2_bits(__floats2half2_rn(f[2 * i], f[2 * i + 1]));
        *reinterpret_cast<uint4*>(smem + OFF_A + aswoff) =
            make_uint4(hw[0], hw[1], hw[2], hw[3]);
        *reinterpret_cast<uint4*>(smem + OFF_A + aswoff + 16) =
            make_uint4(hw[4], hw[5], hw[6], hw[7]);
        cp_wait0();
    }
    __syncthreads();

    #pragma unroll 1
    for (int ch = 0; ch < 16; ch++) {
        const uint32_t st = sb + (uint32_t)(ch & 1) * STAGE_SZ;
        const uint32_t nstb = sb + (uint32_t)((ch + 1) & 1) * STAGE_SZ;

        // ---- issue next stage's loads ----
        if (ch < 15) {
            const int koff = (ch + 1) * 32;
            #pragma unroll
            for (int c = 0; c < 4; c++)
                cp16(nstb + OFF_B + bswrow + c * 16, bgp + koff + c * 8);
            cp_commit();
            #pragma unroll
            for (int i = 0; i < 4; i++)
                pa[i] = reinterpret_cast<const float4*>(aptr + koff)[i];
        }

        // ---- compute this stage: 2 k16-steps ----
        #pragma unroll
        for (int ks = 0; ks < 2; ks++) {
            const uint32_t kb = (uint32_t)(ks * 32) + lkb;
            uint32_t am[4][4];
            uint32_t bh[8][2];

            #pragma unroll
            for (int mb = 0; mb < 4; mb++)
                ldm_x4(am[mb], st + OFF_A +
                               (uint32_t)((wm + mb * 16 + (int)lrow) * ROWB) + kb);
            #pragma unroll
            for (int nb = 0; nb < 4; nb++) {
                uint32_t r[4];
                ldm_x4(r, st + OFF_B +
                          (uint32_t)((wn + nb * 16 + (int)lrow) * ROWB) + kb);
                bh[2 * nb][0] = r[0]; bh[2 * nb + 1][0] = r[1];
                bh[2 * nb][1] = r[2]; bh[2 * nb + 1][1] = r[3];
            }
            #pragma unroll
            for (int mb = 0; mb < 4; mb++)
                #pragma unroll
                for (int ng = 0; ng < 8; ng++)
                    mma_f16(acc[mb][ng], am[mb], bh[ng][0], bh[ng][1]);
        }

        // ---- convert + store next A stage ----
        if (ch < 15) {
            const float* f = reinterpret_cast<const float*>(pa);
            char* nst = smem + ((ch + 1) & 1) * STAGE_SZ;
            uint32_t hw[8];
            #pragma unroll
            for (int i = 0; i < 8; i++)
                hw[i] = h2_bits(__floats2half2_rn(f[2 * i], f[2 * i + 1]));
            *reinterpret_cast<uint4*>(nst + OFF_A + aswoff) =
                make_uint4(hw[0], hw[1], hw[2], hw[3]);
            *reinterpret_cast<uint4*>(nst + OFF_A + aswoff + 16) =
                make_uint4(hw[4], hw[5], hw[6], hw[7]);
            cp_wait0();
        }
        __syncthreads();
    }

    // ---- epilogue: acc regs -> xp (fp16) ----
    {
        #pragma unroll
        for (int mb = 0; mb < 4; mb++) {
            const int row0 = bm + wm + mb * 16 + grp;
            #pragma unroll
            for (int ng = 0; ng < 8; ng++) {
                const int col = bn + wn + ng * 8 + tg * 2;
                *reinterpret_cast<uint32_t*>(&g_xp[(size_t)row0 * 512 + col]) =
                    h2_bits(__floats2half2_rn(acc[mb][ng][0], acc[mb][ng][1]));
                *reinterpret_cast<uint32_t*>(&g_xp[(size_t)(row0 + 8) * 512 + col]) =
                    h2_bits(__floats2half2_rn(acc[mb][ng][2], acc[mb][ng][3]));
            }
        }
    }
}

// ---------------- scan: h_t = relu(xp_t + b + u*h_{t-1}) ----------------
// One thread per (b, r) -- R10's proven shape. Reads fp16 xp, writes fp32 out.
__global__ __launch_bounds__(256) void indrnn_scan(
    float* __restrict__ out,         // [64, 1024, 512]
    const float* __restrict__ u,     // [512]
    const float* __restrict__ bias)  // [512]
{
    const int T = 1024;
    const int R = 512;
    int idx = blockIdx.x * blockDim.x + threadIdx.x;  // 0..32767
    int b = idx >> 9;
    int r = idx & 511;

    float uu = u[r];
    float bb = bias[r];
    float h = 1.0f;
    const __half* ph = g_xp + (size_t)b * T * R + r;
    float* po = out + (size_t)b * T * R + r;

    #pragma unroll 1
    for (int t0 = 0; t0 < T; t0 += 32) {
        float v[32];
        #pragma unroll
        for (int j = 0; j < 32; j++)
            v[j] = __half2float(ph[(t0 + j) * R]);
        #pragma unroll
        for (int j = 0; j < 32; j++) {
            h = fmaxf(fmaf(uu, h, v[j] + bb), 0.0f);
            v[j] = h;
        }
        #pragma unroll
        for (int j = 0; j < 32; j++)
            po[(t0 + j) * R] = v[j];
    }
}

// ---------------- launch ----------------
extern "C" void kernel_launch(void* const* d_in, const int* in_sizes, int n_in,
                              void* d_out, int out_size)
{
    const float* x  = (const float*)d_in[0];  // [64,1024,512]
    const float* W  = (const float*)d_in[1];  // [512,512]
    const float* u  = (const float*)d_in[2];  // [512]
    const float* b  = (const float*)d_in[3];  // [512]
    float* out = (float*)d_out;               // [64,1024,512]

    (void)in_sizes; (void)n_in; (void)out_size;

    cudaFuncSetAttribute(indrnn_gemm_f16,
                         cudaFuncAttributeMaxDynamicSharedMemorySize, GEMM_SMEM);

    conv_w<<<1024, 256>>>(W);

    dim3 ggrid(2, 512);  // x = n-tile, y = m-tile
    indrnn_gemm_f16<<<ggrid, 256, GEMM_SMEM>>>(x);

    indrnn_scan<<<128, 256>>>(out, u, b);
}